// round 9
// baseline (speedup 1.0000x reference)
#include <cuda_runtime.h>
#include <cstdint>
#include <cstddef>

// Problem dims
#define TOKENS_N 8192
#define IN_F     4096
#define OUT_F    4096

// GEMM tiling
#define BM      128
#define BN      128
#define BK      32
#define STAGES  3
#define NCHUNK  (IN_F / BK)            // 128

// smem: stride 36 floats (=144B, 16B aligned, conflict-free fragment loads)
#define LDS_STRIDE   36
#define TILE_FLOATS  (BM * LDS_STRIDE)            // 4608 floats = 18432 B
#define STAGE_FLOATS (2 * TILE_FLOATS)            // A then B
#define SMEM_FLOATS  (STAGES * STAGE_FLOATS)      // 27648 floats = 110592 B

// 64MB dense-weight scratch (device global: allowed; no runtime allocation)
__device__ float g_W[(size_t)OUT_F * IN_F];

// ---------------------------------------------------------------------------
// helpers
// ---------------------------------------------------------------------------
__device__ __forceinline__ uint32_t smem_u32(const void* p) {
    uint32_t a;
    asm("{ .reg .u64 t; cvta.to.shared.u64 t, %1; cvt.u32.u64 %0, t; }"
        : "=r"(a) : "l"(p));
    return a;
}

__device__ __forceinline__ void cp_async16(uint32_t dst, const void* src) {
    asm volatile("cp.async.cg.shared.global [%0], [%1], 16;" :: "r"(dst), "l"(src));
}
#define CP_COMMIT() asm volatile("cp.async.commit_group;" ::: "memory")
#define CP_WAIT(n)  asm volatile("cp.async.wait_group %0;" :: "n"(n) : "memory")

// fp32 -> tf32 with round-to-nearest (unbiased; halves error vs truncation)
__device__ __forceinline__ uint32_t f2tf32(float f) {
    uint32_t r;
    asm("cvt.rna.tf32.f32 %0, %1;" : "=r"(r) : "f"(f));
    return r;
}

__device__ __forceinline__ void mma_tf32(float& c0, float& c1, float& c2, float& c3,
                                         uint32_t a0, uint32_t a1, uint32_t a2, uint32_t a3,
                                         uint32_t b0, uint32_t b1) {
    asm volatile(
        "mma.sync.aligned.m16n8k8.row.col.f32.tf32.tf32.f32 "
        "{%0,%1,%2,%3}, {%4,%5,%6,%7}, {%8,%9}, {%0,%1,%2,%3};"
        : "+f"(c0), "+f"(c1), "+f"(c2), "+f"(c3)
        : "r"(a0), "r"(a1), "r"(a2), "r"(a3), "r"(b0), "r"(b1));
}

// ---------------------------------------------------------------------------
// Kernel 1: materialize dense W[o, i] = weight[idx[o*IN_F + i]]
// ---------------------------------------------------------------------------
__global__ void __launch_bounds__(256)
materialize_w(const int* __restrict__ idx, const float* __restrict__ w) {
    size_t i = (size_t)blockIdx.x * 256 + threadIdx.x;   // one int4 / float4 per thread
    int4 v = reinterpret_cast<const int4*>(idx)[i];
    float4 o;
    o.x = __ldg(w + v.x);
    o.y = __ldg(w + v.y);
    o.z = __ldg(w + v.z);
    o.w = __ldg(w + v.w);
    reinterpret_cast<float4*>(g_W)[i] = o;
}

// ---------------------------------------------------------------------------
// Kernel 2: tf32 mma.sync GEMM  Out[m,n] = sum_k X[m,k] * W[n,k] + bias[n]
// 256 threads = 8 warps in a 2(M) x 4(N) grid; warp tile 64x32.
// ---------------------------------------------------------------------------
extern "C" __global__ void __launch_bounds__(256, 2)
hashed_gemm(const float* __restrict__ X, const float* __restrict__ bias,
            float* __restrict__ Out) {
    __shared__ float smem[SMEM_FLOATS];

    const int tid  = threadIdx.x;
    const int wid  = tid >> 5;
    const int lane = tid & 31;
    const int warp_m = wid >> 2;          // 0..1
    const int warp_n = wid & 3;           // 0..3
    const int qr = lane >> 2;             // 0..7
    const int qk = lane & 3;              // 0..3

    const int n0 = blockIdx.x * BN;
    const int m0 = blockIdx.y * BM;

    const uint32_t sb = smem_u32(smem);

    // --- cp.async mapping: tile = 128 rows x 8 x 16B segments; 4 chunks/thread
    const int crow = tid >> 1;                      // 0..127 (row for t=0,1; +? see below)
    // We map 1024 chunks as idx = tid + t*256 -> row = idx/8, seg = idx%8.
    // (computed in the loop to keep regs down)

    auto issue_chunk = [&](int c, int stage) {
        const uint32_t abase = sb + (uint32_t)(stage * STAGE_FLOATS) * 4u;
        const uint32_t bbase = abase + (uint32_t)TILE_FLOATS * 4u;
        const float* gx = X   + (size_t)m0 * IN_F + c * BK;
        const float* gw = g_W + (size_t)n0 * IN_F + c * BK;
#pragma unroll
        for (int t = 0; t < 4; t++) {
            int idx = tid + t * 256;
            int row = idx >> 3;
            int seg = idx & 7;
            uint32_t soff = (uint32_t)(row * LDS_STRIDE + seg * 4) * 4u;
            cp_async16(abase + soff, gx + (size_t)row * IN_F + seg * 4);
            cp_async16(bbase + soff, gw + (size_t)row * IN_F + seg * 4);
        }
    };

    // Prologue: fill STAGES-1 stages
#pragma unroll
    for (int c = 0; c < STAGES - 1; c++) {
        issue_chunk(c, c);
        CP_COMMIT();
    }

    float acc[4][4][4];
#pragma unroll
    for (int mt = 0; mt < 4; mt++)
#pragma unroll
        for (int nt = 0; nt < 4; nt++)
#pragma unroll
            for (int q = 0; q < 4; q++) acc[mt][nt][q] = 0.0f;

    const float* As_base = smem;                       // per-stage offsets added below
    for (int c = 0; c < NCHUNK; ++c) {
        CP_WAIT(STAGES - 2);
        __syncthreads();

        // prefetch chunk c+STAGES-1 into the stage freed by chunk c-1
        const int nk = c + STAGES - 1;
        if (nk < NCHUNK) issue_chunk(nk, nk % STAGES);
        CP_COMMIT();

        const float* As = As_base + (c % STAGES) * STAGE_FLOATS;
        const float* Bs = As + TILE_FLOATS;

#pragma unroll
        for (int kk = 0; kk < 4; kk++) {
            const int k0 = kk * 8;
            // A fragments: 4 m-tiles
            uint32_t af[4][4];
#pragma unroll
            for (int mt = 0; mt < 4; mt++) {
                const int r = warp_m * 64 + mt * 16 + qr;
                const float* p0 = As + r * LDS_STRIDE + k0 + qk;
                const float* p1 = As + (r + 8) * LDS_STRIDE + k0 + qk;
                af[mt][0] = f2tf32(p0[0]);
                af[mt][1] = f2tf32(p1[0]);
                af[mt][2] = f2tf32(p0[4]);
                af[mt][3] = f2tf32(p1[4]);
            }
#pragma unroll
            for (int nt = 0; nt < 4; nt++) {
                const int rb = warp_n * 32 + nt * 8 + qr;
                const float* pb = Bs + rb * LDS_STRIDE + k0 + qk;
                uint32_t b0 = f2tf32(pb[0]);
                uint32_t b1 = f2tf32(pb[4]);
#pragma unroll
                for (int mt = 0; mt < 4; mt++) {
                    mma_tf32(acc[mt][nt][0], acc[mt][nt][1],
                             acc[mt][nt][2], acc[mt][nt][3],
                             af[mt][0], af[mt][1], af[mt][2], af[mt][3], b0, b1);
                }
            }
        }
    }

    // Epilogue: add bias, store float2 per (row, nt)
#pragma unroll
    for (int mt = 0; mt < 4; mt++) {
        const int r = m0 + warp_m * 64 + mt * 16 + qr;
#pragma unroll
        for (int nt = 0; nt < 4; nt++) {
            const int col = n0 + warp_n * 32 + nt * 8 + 2 * qk;
            const float bx = __ldg(bias + col);
            const float by = __ldg(bias + col + 1);
            float2 v0 = make_float2(acc[mt][nt][0] + bx, acc[mt][nt][1] + by);
            float2 v1 = make_float2(acc[mt][nt][2] + bx, acc[mt][nt][3] + by);
            *reinterpret_cast<float2*>(Out + (size_t)r * OUT_F + col) = v0;
            *reinterpret_cast<float2*>(Out + (size_t)(r + 8) * OUT_F + col) = v1;
        }
    }
}

// ---------------------------------------------------------------------------
// Launch
// ---------------------------------------------------------------------------
extern "C" void kernel_launch(void* const* d_in, const int* in_sizes, int n_in,
                              void* d_out, int out_size) {
    const float* x    = (const float*)d_in[0];   // [8192, 4096] f32
    const float* w    = (const float*)d_in[1];   // [65536] f32
    const float* bias = (const float*)d_in[2];   // [4096] f32
    const int*   idx  = (const int*)d_in[3];     // [4096*4096] i32
    float* out = (float*)d_out;                  // [8192, 4096] f32

    // Stage 1: gather dense weight into g_W (64MB), fully coalesced.
    const size_t n_vec4 = (size_t)OUT_F * IN_F / 4;          // 4,194,304
    materialize_w<<<(unsigned)(n_vec4 / 256), 256>>>(idx, w);

    // Stage 2: tf32 mma.sync GEMM + bias epilogue.
    dim3 grid(OUT_F / BN, TOKENS_N / BM);                    // (32, 64)
    hashed_gemm<<<grid, 256>>>(x, bias, out);
}

// round 10
// speedup vs baseline: 2.2561x; 2.2561x over previous
#include <cuda_runtime.h>
#include <cuda_fp16.h>
#include <cstdint>
#include <cstddef>

// Problem dims
#define TOKENS_N 8192
#define IN_F     4096
#define OUT_F    4096

// GEMM tiling
#define BM      128
#define BN      128
#define BK      64                     // halves per K-chunk (128 bytes/row)
#define STAGES  3
#define NCHUNK  (IN_F / BK)            // 64

// smem: padded row stride 72 halves = 144 B (36 banks = 4 mod 32 -> ldmatrix
// 8-row phases hit all 32 banks exactly once; conflict-free)
#define ROW_BYTES    144
#define TILE_BYTES   (BM * ROW_BYTES)           // 18432
#define STAGE_BYTES  (2 * TILE_BYTES)           // 36864 (A then B)
#define SMEM_BYTES   (STAGES * STAGE_BYTES)     // 110592 (same as passing R9 kernel)

// Pre-converted operands (device globals: allowed scratch)
__device__ __half g_X [(size_t)TOKENS_N * IN_F];   // 64 MB
__device__ __half g_Wh[(size_t)OUT_F   * IN_F];    // 32 MB

// ---------------------------------------------------------------------------
// helpers
// ---------------------------------------------------------------------------
__device__ __forceinline__ uint32_t smem_u32(const void* p) {
    uint32_t a;
    asm("{ .reg .u64 t; cvta.to.shared.u64 t, %1; cvt.u32.u64 %0, t; }"
        : "=r"(a) : "l"(p));
    return a;
}

__device__ __forceinline__ void cp_async16(uint32_t dst, const void* src) {
    asm volatile("cp.async.cg.shared.global [%0], [%1], 16;" :: "r"(dst), "l"(src));
}
#define CP_COMMIT() asm volatile("cp.async.commit_group;" ::: "memory")
#define CP_WAIT(n)  asm volatile("cp.async.wait_group %0;" :: "n"(n) : "memory")

__device__ __forceinline__ void ldsm_x4(uint32_t* r, uint32_t addr) {
    asm volatile("ldmatrix.sync.aligned.m8n8.x4.shared.b16 {%0,%1,%2,%3}, [%4];"
        : "=r"(r[0]), "=r"(r[1]), "=r"(r[2]), "=r"(r[3]) : "r"(addr));
}

__device__ __forceinline__ void mma_f16(float* c, const uint32_t* a,
                                        uint32_t b0, uint32_t b1) {
    asm volatile(
        "mma.sync.aligned.m16n8k16.row.col.f32.f16.f16.f32 "
        "{%0,%1,%2,%3}, {%4,%5,%6,%7}, {%8,%9}, {%0,%1,%2,%3};"
        : "+f"(c[0]), "+f"(c[1]), "+f"(c[2]), "+f"(c[3])
        : "r"(a[0]), "r"(a[1]), "r"(a[2]), "r"(a[3]), "r"(b0), "r"(b1));
}

__device__ __forceinline__ uint32_t h2u(__half2 h) {
    return *reinterpret_cast<uint32_t*>(&h);
}

// ---------------------------------------------------------------------------
// Kernel 1: X fp32 -> fp16  (8 elements / thread, 16B stores)
// ---------------------------------------------------------------------------
__global__ void __launch_bounds__(256)
conv_x(const float* __restrict__ x) {
    size_t i = (size_t)blockIdx.x * 256 + threadIdx.x;
    const float4* p = reinterpret_cast<const float4*>(x) + 2 * i;
    float4 a = p[0], b = p[1];
    uint4 o;
    o.x = h2u(__floats2half2_rn(a.x, a.y));
    o.y = h2u(__floats2half2_rn(a.z, a.w));
    o.z = h2u(__floats2half2_rn(b.x, b.y));
    o.w = h2u(__floats2half2_rn(b.z, b.w));
    reinterpret_cast<uint4*>(g_X)[i] = o;
}

// ---------------------------------------------------------------------------
// Kernel 2: gather + convert  W[o,i] = (half)weight[idx[o*IN_F+i]]
// 8 elements / thread: two int4 index loads, 8 gathers, one 16B store.
// ---------------------------------------------------------------------------
__global__ void __launch_bounds__(256)
materialize_w(const int* __restrict__ idx, const float* __restrict__ w) {
    size_t i = (size_t)blockIdx.x * 256 + threadIdx.x;
    const int4* ip = reinterpret_cast<const int4*>(idx) + 2 * i;
    int4 v0 = ip[0], v1 = ip[1];
    uint4 o;
    o.x = h2u(__floats2half2_rn(__ldg(w + v0.x), __ldg(w + v0.y)));
    o.y = h2u(__floats2half2_rn(__ldg(w + v0.z), __ldg(w + v0.w)));
    o.z = h2u(__floats2half2_rn(__ldg(w + v1.x), __ldg(w + v1.y)));
    o.w = h2u(__floats2half2_rn(__ldg(w + v1.z), __ldg(w + v1.w)));
    reinterpret_cast<uint4*>(g_Wh)[i] = o;
}

// ---------------------------------------------------------------------------
// Kernel 3: fp16 mma.sync GEMM  Out[m,n] = sum_k X[m,k]*W[n,k] + bias[n]
// 256 threads = 8 warps, 2(M) x 4(N), warp tile 64x32. Zero CVTs in loop;
// fragments via ldmatrix.x4 on a conflict-free 144B-stride layout.
// ---------------------------------------------------------------------------
extern "C" __global__ void __launch_bounds__(256, 2)
hashed_gemm(const float* __restrict__ bias, float* __restrict__ Out) {
    __shared__ __align__(16) unsigned char smem[SMEM_BYTES];

    const int tid  = threadIdx.x;
    const int wid  = tid >> 5;
    const int lane = tid & 31;
    const int warp_m = wid >> 2;          // 0..1
    const int warp_n = wid & 3;           // 0..3
    const int qr = lane >> 2;             // 0..7
    const int qk = lane & 3;              // 0..3

    const int n0 = blockIdx.x * BN;
    const int m0 = blockIdx.y * BM;

    const uint32_t sb = smem_u32(smem);

    // cp.async mapping: tile = 128 rows x 8 x 16B segments; 4 A + 4 B per thread
    auto issue_chunk = [&](int c, int stage) {
        const uint32_t abase = sb + (uint32_t)(stage * STAGE_BYTES);
        const uint32_t bbase = abase + TILE_BYTES;
        const __half* gx = g_X  + (size_t)m0 * IN_F + c * BK;
        const __half* gw = g_Wh + (size_t)n0 * IN_F + c * BK;
#pragma unroll
        for (int t = 0; t < 4; t++) {
            int idx = tid + t * 256;          // 0..1023
            int row = idx >> 3;
            int seg = idx & 7;
            uint32_t soff = (uint32_t)(row * ROW_BYTES + seg * 16);
            cp_async16(abase + soff, gx + (size_t)row * IN_F + seg * 8);
            cp_async16(bbase + soff, gw + (size_t)row * IN_F + seg * 8);
        }
    };

    // ldmatrix per-lane base offsets (bytes within tile)
    // A x4: lanes 0-15 -> rows 0-15 @ k, lanes 16-31 -> rows 0-15 @ k+8 halves
    const uint32_t a_off = (uint32_t)((warp_m * 64 + (lane & 15)) * ROW_BYTES
                                      + (lane >> 4) * 16);
    // B x4: lanes 0-7 rows n..n+7 @k (b0,nt even), 8-15 same rows @k+8 (b1),
    //       16-23 rows n+8..15 @k (b0,nt odd), 24-31 @k+8 (b1)
    const uint32_t b_off = (uint32_t)((warp_n * 32 + (lane & 7) + ((lane >> 4) & 1) * 8) * ROW_BYTES
                                      + ((lane >> 3) & 1) * 16);

    // Prologue: fill STAGES-1 stages
#pragma unroll
    for (int c = 0; c < STAGES - 1; c++) {
        issue_chunk(c, c);
        CP_COMMIT();
    }

    float acc[4][4][4];
#pragma unroll
    for (int mt = 0; mt < 4; mt++)
#pragma unroll
        for (int nt = 0; nt < 4; nt++)
#pragma unroll
            for (int q = 0; q < 4; q++) acc[mt][nt][q] = 0.0f;

    for (int c = 0; c < NCHUNK; ++c) {
        CP_WAIT(STAGES - 2);
        __syncthreads();

        const int nk = c + STAGES - 1;
        if (nk < NCHUNK) issue_chunk(nk, nk % STAGES);
        CP_COMMIT();

        const uint32_t As = sb + (uint32_t)((c % STAGES) * STAGE_BYTES);
        const uint32_t Bs = As + TILE_BYTES;

#pragma unroll
        for (int kk = 0; kk < BK / 16; kk++) {      // 4 k16 steps
            const uint32_t kb = (uint32_t)(kk * 32); // 16 halves = 32 bytes
            uint32_t af[4][4];
#pragma unroll
            for (int mt = 0; mt < 4; mt++)
                ldsm_x4(af[mt], As + a_off + (uint32_t)(mt * 16 * ROW_BYTES) + kb);
            uint32_t bf[2][4];
#pragma unroll
            for (int pr = 0; pr < 2; pr++)
                ldsm_x4(bf[pr], Bs + b_off + (uint32_t)(pr * 16 * ROW_BYTES) + kb);
#pragma unroll
            for (int nt = 0; nt < 4; nt++) {
                const uint32_t b0 = bf[nt >> 1][(nt & 1) * 2];
                const uint32_t b1 = bf[nt >> 1][(nt & 1) * 2 + 1];
#pragma unroll
                for (int mt = 0; mt < 4; mt++)
                    mma_f16(acc[mt][nt], af[mt], b0, b1);
            }
        }
    }

    // Epilogue: add bias, store float2 per (row, nt)  (D layout same as k16 mma)
#pragma unroll
    for (int mt = 0; mt < 4; mt++) {
        const int r = m0 + warp_m * 64 + mt * 16 + qr;
#pragma unroll
        for (int nt = 0; nt < 4; nt++) {
            const int col = n0 + warp_n * 32 + nt * 8 + 2 * qk;
            const float bx = __ldg(bias + col);
            const float by = __ldg(bias + col + 1);
            float2 v0 = make_float2(acc[mt][nt][0] + bx, acc[mt][nt][1] + by);
            float2 v1 = make_float2(acc[mt][nt][2] + bx, acc[mt][nt][3] + by);
            *reinterpret_cast<float2*>(Out + (size_t)r * OUT_F + col) = v0;
            *reinterpret_cast<float2*>(Out + (size_t)(r + 8) * OUT_F + col) = v1;
        }
    }
}

// ---------------------------------------------------------------------------
// Launch
// ---------------------------------------------------------------------------
extern "C" void kernel_launch(void* const* d_in, const int* in_sizes, int n_in,
                              void* d_out, int out_size) {
    const float* x    = (const float*)d_in[0];   // [8192, 4096] f32
    const float* w    = (const float*)d_in[1];   // [65536] f32
    const float* bias = (const float*)d_in[2];   // [4096] f32
    const int*   idx  = (const int*)d_in[3];     // [4096*4096] i32
    float* out = (float*)d_out;                  // [8192, 4096] f32

    // Stage 1a: X -> fp16 (64 MB), fully coalesced.
    const unsigned gx_blocks = (unsigned)(((size_t)TOKENS_N * IN_F / 8) / 256);  // 16384
    conv_x<<<gx_blocks, 256>>>(x);

    // Stage 1b: gather dense weight -> fp16 (32 MB), fully coalesced.
    const unsigned gw_blocks = (unsigned)(((size_t)OUT_F * IN_F / 8) / 256);     // 8192
    materialize_w<<<gw_blocks, 256>>>(idx, w);

    // Stage 2: fp16 tensor-core GEMM + bias epilogue.
    dim3 grid(OUT_F / BN, TOKENS_N / BM);                    // (32, 64)
    hashed_gemm<<<grid, 256>>>(bias, out);
}